// round 3
// baseline (speedup 1.0000x reference)
#include <cuda_runtime.h>
#include <cstdint>

// SpikeFP32Adder — integer re-implementation of the soft-gate FP32 adder.
// R3: ballot-free packing. Lane l accumulates column (31-l) of 32 rows into a
// bit-column word (1 SHF + 1 LOP3 per element), then a 5-stage shfl_xor
// 32x32 bit-matrix transpose hands lane r its row's IEEE-layout word.
// Unpack uses shfl.idx + STG.128 (4 rows / 512B per store instruction).

__device__ __forceinline__ unsigned spike_fp32_add(unsigned ra, unsigned rb) {
    const unsigned sa = ra >> 31, sb = rb >> 31;
    const unsigned ea = (ra >> 23) & 0xFFu, eb = (rb >> 23) & 0xFFu;

    const unsigned eae = ea ? ea : 1u;                      // e_eff
    const unsigned ebe = eb ? eb : 1u;
    const unsigned manta = (ra & 0x7FFFFFu) | ((ea ? 1u : 0u) << 23);
    const unsigned mantb = (rb & 0x7FFFFFu) | ((eb ? 1u : 0u) << 23);

    const bool exp_eq = (eae == ebe);
    const bool a_ge_b = (eae > ebe) || (exp_eq && (manta >= mantb));
    const bool abs_eq = exp_eq && (manta == mantb);

    const unsigned ediff = a_ge_b ? (eae - ebe) : (ebe - eae);
    const bool big = (ediff >= 24u);                        // is_big_diff
    const unsigned shift = big ? 0u : ediff;

    const unsigned emax = a_ge_b ? eae : ebe;
    const unsigned Ml  = (a_ge_b ? manta : mantb) << 4;     // 28-bit
    const unsigned Ms0 = (a_ge_b ? mantb : manta) << 4;

    const bool sticky = (Ms0 & ((1u << shift) - 1u)) != 0u;
    const unsigned Ms = Ms0 >> shift;

    const unsigned ds = sa ^ sb;                            // diff sign
    const bool exact_cancel = (ds != 0u) && abs_eq;
    const unsigned s_large = a_ge_b ? sa : sb;

    const unsigned sum = Ml + Ms;
    const unsigned diff = (Ml - Ms - ((ds && sticky) ? 1u : 0u)) & 0xFFFFFFFu;
    const unsigned res_carry = ds ? 0u : ((sum >> 28) & 1u);
    const unsigned mant_res = ds ? diff : (sum & 0xFFFFFFFu);

    const unsigned lzc = (unsigned)__clz(mant_res) - 4u;    // 0..28
    const bool underflow = (lzc >= emax);
    const unsigned norm_m = (mant_res << lzc) & 0xFFFFFFFu;

    const unsigned e_after  = (emax - lzc) & 0xFFu;
    const unsigned e_plus1  = (emax + 1u) & 0xFFu;
    const unsigned e_normal = underflow ? 0u : e_after;
    const unsigned final_e  = res_carry ? e_plus1 : e_normal;

    const unsigned m_pre = res_carry ? ((mant_res >> 5) & 0x7FFFFFu)
                                     : ((norm_m  >> 4) & 0x7FFFFFu);
    const unsigned r_pre = res_carry ? ((mant_res >> 4) & 1u)
                                     : ((norm_m  >> 3) & 1u);
    const bool st_raw = res_carry ? ((mant_res & 0xFu) != 0u)
                                  : ((norm_m  & 0x7u) != 0u);
    const bool st_pre = st_raw || ((ds == 0u) && sticky);

    const unsigned m_sel = underflow ? ((mant_res >> 5) & 0x7FFFFFu) : m_pre;
    const unsigned L = m_sel & 1u;
    const unsigned do_round =
        ((r_pre != 0u) && (st_pre || (L != 0u)) && !underflow) ? 1u : 0u;

    // Circuit quirk: round-adder carry-out is structurally 0 — mantissa wraps
    // to 0 on rounding overflow WITHOUT exponent increment.
    const unsigned m_final = (m_sel + do_round) & 0x7FFFFFu;

    const bool inf = (final_e == 0xFFu);
    unsigned cs = exact_cancel ? 0u : s_large;
    unsigned ce = exact_cancel ? 0u : final_e;
    unsigned cm = exact_cancel ? 0u : m_final;
    cs = inf ? s_large : cs;
    ce = inf ? 0xFFu   : ce;
    cm = inf ? 0u      : cm;

    const unsigned normal = (cs << 31) | (ce << 23) | cm;
    const unsigned larger = a_ge_b ? ra : rb;
    return big ? larger : normal;
}

// 32x32 bit-matrix transpose across a warp: input lane c holds word whose
// bit r is M[r][c]; output lane r holds word whose bit c is M[r][c].
__device__ __forceinline__ unsigned bit_transpose32(unsigned t, unsigned lane) {
    unsigned y;
    y = __shfl_xor_sync(0xFFFFFFFFu, t, 16);
    t = (lane & 16) ? ((t & 0xFFFF0000u) | (y >> 16))
                    : ((t & 0x0000FFFFu) | (y << 16));
    y = __shfl_xor_sync(0xFFFFFFFFu, t, 8);
    t = (lane & 8) ? ((t & 0xFF00FF00u) | ((y >> 8) & 0x00FF00FFu))
                   : ((t & 0x00FF00FFu) | ((y << 8) & 0xFF00FF00u));
    y = __shfl_xor_sync(0xFFFFFFFFu, t, 4);
    t = (lane & 4) ? ((t & 0xF0F0F0F0u) | ((y >> 4) & 0x0F0F0F0Fu))
                   : ((t & 0x0F0F0F0Fu) | ((y << 4) & 0xF0F0F0F0u));
    y = __shfl_xor_sync(0xFFFFFFFFu, t, 2);
    t = (lane & 2) ? ((t & 0xCCCCCCCCu) | ((y >> 2) & 0x33333333u))
                   : ((t & 0x33333333u) | ((y << 2) & 0xCCCCCCCCu));
    y = __shfl_xor_sync(0xFFFFFFFFu, t, 1);
    t = (lane & 1) ? ((t & 0xAAAAAAAAu) | ((y >> 1) & 0x55555555u))
                   : ((t & 0x55555555u) | ((y << 1) & 0xAAAAAAAAu));
    return t;
}

__global__ void __launch_bounds__(256)
spike_adder_kernel(const unsigned* __restrict__ A,
                   const unsigned* __restrict__ B,
                   float* __restrict__ O,
                   int nwarpTiles) {
    const int warpId = blockIdx.x * (blockDim.x >> 5) + (threadIdx.x >> 5);
    const unsigned lane = threadIdx.x & 31;
    if (warpId >= nwarpTiles) return;

    const size_t elemBase = (size_t)warpId * 32 * 32;   // 32 rows * 32 cols
    const unsigned* pa = A + elemBase + (31 - lane);    // lane l -> column 31-l
    const unsigned* pb = B + elemBase + (31 - lane);

    // Pack: accumulate bit 23 (set iff value==1.0f) of row i into bit i.
    unsigned ca = 0u, cb = 0u;
    #pragma unroll
    for (int i = 0; i < 32; i++) {
        const unsigned ua = __ldg(pa + i * 32);
        const unsigned ub = __ldg(pb + i * 32);
        if (i <= 23) {
            ca |= (ua >> (23 - i)) & (1u << i);
            cb |= (ub >> (23 - i)) & (1u << i);
        } else {
            ca |= (ua << (i - 23)) & (1u << i);
            cb |= (ub << (i - 23)) & (1u << i);
        }
    }

    // Transpose: lane r now holds row r's word; bit position p = column 31-p,
    // which is exactly the IEEE layout (bit31 = sign = column 0).
    const unsigned ra = bit_transpose32(ca, lane);
    const unsigned rb = bit_transpose32(cb, lane);

    const unsigned res = spike_fp32_add(ra, rb);        // per-lane row

    // Unpack: iteration i stores rows 4i..4i+3 (512B) with STG.128.
    float* po = O + elemBase;
    #pragma unroll
    for (int i = 0; i < 8; i++) {
        const int src = i * 4 + (lane >> 3);
        const unsigned w = __shfl_sync(0xFFFFFFFFu, res, src);
        const unsigned w2 = w << ((lane & 7) * 4);
        float4 f;
        f.x = __uint_as_float(((unsigned)((int)(w2     ) >> 31)) & 0x3F800000u);
        f.y = __uint_as_float(((unsigned)((int)(w2 << 1) >> 31)) & 0x3F800000u);
        f.z = __uint_as_float(((unsigned)((int)(w2 << 2) >> 31)) & 0x3F800000u);
        f.w = __uint_as_float(((unsigned)((int)(w2 << 3) >> 31)) & 0x3F800000u);
        *reinterpret_cast<float4*>(po + i * 128 + (lane >> 3) * 32 + (lane & 7) * 4) = f;
    }
}

// Scalar tail kernel (warp-per-row) for nrows % 32 != 0.
__global__ void spike_adder_tail(const float* __restrict__ A,
                                 const float* __restrict__ B,
                                 float* __restrict__ O,
                                 int rowStart, int nrows) {
    const int row = rowStart + blockIdx.x;
    const int lane = threadIdx.x & 31;
    if (row >= nrows) return;
    const size_t base = (size_t)row * 32 + lane;
    const unsigned ua = __ballot_sync(0xFFFFFFFFu, A[base] != 0.0f);
    const unsigned ub = __ballot_sync(0xFFFFFFFFu, B[base] != 0.0f);
    const unsigned res = spike_fp32_add(__brev(ua), __brev(ub));
    const unsigned f = ((unsigned)((int)(res << lane) >> 31)) & 0x3F800000u;
    O[base] = __uint_as_float(f);
}

extern "C" void kernel_launch(void* const* d_in, const int* in_sizes, int n_in,
                              void* d_out, int out_size) {
    const float* A = (const float*)d_in[0];
    const float* B = (const float*)d_in[1];
    float* O = (float*)d_out;

    const int nrows = in_sizes[0] / 32;
    const int nwarpTiles = nrows / 32;
    const int tailRows = nrows - nwarpTiles * 32;

    if (nwarpTiles > 0) {
        const int threads = 256;
        const int warpsPerBlock = threads / 32;
        const int blocks = (nwarpTiles + warpsPerBlock - 1) / warpsPerBlock;
        spike_adder_kernel<<<blocks, threads>>>(
            (const unsigned*)A, (const unsigned*)B, O, nwarpTiles);
    }
    if (tailRows > 0) {
        spike_adder_tail<<<tailRows, 32>>>(A, B, O, nwarpTiles * 32, nrows);
    }
}

// round 4
// speedup vs baseline: 1.0626x; 1.0626x over previous
#include <cuda_runtime.h>
#include <cstdint>

// SpikeFP32Adder — integer re-implementation of the soft-gate FP32 adder.
// R4: wave-quantization fix. Each warp processes exactly 2 tiles (strided),
// grid sized to fit a single wave (1024 blocks @ 8 blocks/SM resident) so
// there is no 73%-full second wave draining DRAM utilization.

__device__ __forceinline__ unsigned spike_fp32_add(unsigned ra, unsigned rb) {
    const unsigned sa = ra >> 31, sb = rb >> 31;
    const unsigned ea = (ra >> 23) & 0xFFu, eb = (rb >> 23) & 0xFFu;

    const unsigned eae = ea ? ea : 1u;                      // e_eff
    const unsigned ebe = eb ? eb : 1u;
    const unsigned manta = (ra & 0x7FFFFFu) | ((ea ? 1u : 0u) << 23);
    const unsigned mantb = (rb & 0x7FFFFFu) | ((eb ? 1u : 0u) << 23);

    const bool exp_eq = (eae == ebe);
    const bool a_ge_b = (eae > ebe) || (exp_eq && (manta >= mantb));
    const bool abs_eq = exp_eq && (manta == mantb);

    const unsigned ediff = a_ge_b ? (eae - ebe) : (ebe - eae);
    const bool big = (ediff >= 24u);                        // is_big_diff
    const unsigned shift = big ? 0u : ediff;

    const unsigned emax = a_ge_b ? eae : ebe;
    const unsigned Ml  = (a_ge_b ? manta : mantb) << 4;     // 28-bit
    const unsigned Ms0 = (a_ge_b ? mantb : manta) << 4;

    const bool sticky = (Ms0 & ((1u << shift) - 1u)) != 0u;
    const unsigned Ms = Ms0 >> shift;

    const unsigned ds = sa ^ sb;                            // diff sign
    const bool exact_cancel = (ds != 0u) && abs_eq;
    const unsigned s_large = a_ge_b ? sa : sb;

    const unsigned sum = Ml + Ms;
    const unsigned diff = (Ml - Ms - ((ds && sticky) ? 1u : 0u)) & 0xFFFFFFFu;
    const unsigned res_carry = ds ? 0u : ((sum >> 28) & 1u);
    const unsigned mant_res = ds ? diff : (sum & 0xFFFFFFFu);

    const unsigned lzc = (unsigned)__clz(mant_res) - 4u;    // 0..28
    const bool underflow = (lzc >= emax);
    const unsigned norm_m = (mant_res << lzc) & 0xFFFFFFFu;

    const unsigned e_after  = (emax - lzc) & 0xFFu;
    const unsigned e_plus1  = (emax + 1u) & 0xFFu;
    const unsigned e_normal = underflow ? 0u : e_after;
    const unsigned final_e  = res_carry ? e_plus1 : e_normal;

    const unsigned m_pre = res_carry ? ((mant_res >> 5) & 0x7FFFFFu)
                                     : ((norm_m  >> 4) & 0x7FFFFFu);
    const unsigned r_pre = res_carry ? ((mant_res >> 4) & 1u)
                                     : ((norm_m  >> 3) & 1u);
    const bool st_raw = res_carry ? ((mant_res & 0xFu) != 0u)
                                  : ((norm_m  & 0x7u) != 0u);
    const bool st_pre = st_raw || ((ds == 0u) && sticky);

    const unsigned m_sel = underflow ? ((mant_res >> 5) & 0x7FFFFFu) : m_pre;
    const unsigned L = m_sel & 1u;
    const unsigned do_round =
        ((r_pre != 0u) && (st_pre || (L != 0u)) && !underflow) ? 1u : 0u;

    // Circuit quirk: round-adder carry-out is structurally 0 — mantissa wraps
    // to 0 on rounding overflow WITHOUT exponent increment.
    const unsigned m_final = (m_sel + do_round) & 0x7FFFFFu;

    const bool inf = (final_e == 0xFFu);
    unsigned cs = exact_cancel ? 0u : s_large;
    unsigned ce = exact_cancel ? 0u : final_e;
    unsigned cm = exact_cancel ? 0u : m_final;
    cs = inf ? s_large : cs;
    ce = inf ? 0xFFu   : ce;
    cm = inf ? 0u      : cm;

    const unsigned normal = (cs << 31) | (ce << 23) | cm;
    const unsigned larger = a_ge_b ? ra : rb;
    return big ? larger : normal;
}

// 32x32 bit-matrix transpose across a warp.
__device__ __forceinline__ unsigned bit_transpose32(unsigned t, unsigned lane) {
    unsigned y;
    y = __shfl_xor_sync(0xFFFFFFFFu, t, 16);
    t = (lane & 16) ? ((t & 0xFFFF0000u) | (y >> 16))
                    : ((t & 0x0000FFFFu) | (y << 16));
    y = __shfl_xor_sync(0xFFFFFFFFu, t, 8);
    t = (lane & 8) ? ((t & 0xFF00FF00u) | ((y >> 8) & 0x00FF00FFu))
                   : ((t & 0x00FF00FFu) | ((y << 8) & 0xFF00FF00u));
    y = __shfl_xor_sync(0xFFFFFFFFu, t, 4);
    t = (lane & 4) ? ((t & 0xF0F0F0F0u) | ((y >> 4) & 0x0F0F0F0Fu))
                   : ((t & 0x0F0F0F0Fu) | ((y << 4) & 0xF0F0F0F0u));
    y = __shfl_xor_sync(0xFFFFFFFFu, t, 2);
    t = (lane & 2) ? ((t & 0xCCCCCCCCu) | ((y >> 2) & 0x33333333u))
                   : ((t & 0x33333333u) | ((y << 2) & 0xCCCCCCCCu));
    y = __shfl_xor_sync(0xFFFFFFFFu, t, 1);
    t = (lane & 1) ? ((t & 0xAAAAAAAAu) | ((y >> 1) & 0x55555555u))
                   : ((t & 0x55555555u) | ((y << 1) & 0xAAAAAAAAu));
    return t;
}

__device__ __forceinline__ void process_tile(const unsigned* __restrict__ A,
                                             const unsigned* __restrict__ B,
                                             float* __restrict__ O,
                                             int tile, unsigned lane) {
    const size_t elemBase = (size_t)tile * 32 * 32;     // 32 rows * 32 cols
    const unsigned* pa = A + elemBase + (31 - lane);    // lane l -> column 31-l
    const unsigned* pb = B + elemBase + (31 - lane);

    // Pack: bit 23 (set iff value==1.0f) of row i goes to bit i.
    unsigned ca = 0u, cb = 0u;
    #pragma unroll
    for (int i = 0; i < 32; i++) {
        const unsigned ua = __ldcs(pa + i * 32);
        const unsigned ub = __ldcs(pb + i * 32);
        if (i <= 23) {
            ca |= (ua >> (23 - i)) & (1u << i);
            cb |= (ub >> (23 - i)) & (1u << i);
        } else {
            ca |= (ua << (i - 23)) & (1u << i);
            cb |= (ub << (i - 23)) & (1u << i);
        }
    }

    // Transpose -> lane r holds row r's word in IEEE layout.
    const unsigned ra = bit_transpose32(ca, lane);
    const unsigned rb = bit_transpose32(cb, lane);

    const unsigned res = spike_fp32_add(ra, rb);        // per-lane row

    // Unpack: iteration i stores rows 4i..4i+3 (512B) with STG.128.
    float* po = O + elemBase;
    #pragma unroll
    for (int i = 0; i < 8; i++) {
        const int src = i * 4 + (lane >> 3);
        const unsigned w = __shfl_sync(0xFFFFFFFFu, res, src);
        const unsigned w2 = w << ((lane & 7) * 4);
        float4 f;
        f.x = __uint_as_float(((unsigned)((int)(w2     ) >> 31)) & 0x3F800000u);
        f.y = __uint_as_float(((unsigned)((int)(w2 << 1) >> 31)) & 0x3F800000u);
        f.z = __uint_as_float(((unsigned)((int)(w2 << 2) >> 31)) & 0x3F800000u);
        f.w = __uint_as_float(((unsigned)((int)(w2 << 3) >> 31)) & 0x3F800000u);
        *reinterpret_cast<float4*>(po + i * 128 + (lane >> 3) * 32 + (lane & 7) * 4) = f;
    }
}

__global__ void __launch_bounds__(256)
spike_adder_kernel(const unsigned* __restrict__ A,
                   const unsigned* __restrict__ B,
                   float* __restrict__ O,
                   int nwarpTiles, int totalWarps) {
    const int warpId = blockIdx.x * (blockDim.x >> 5) + (threadIdx.x >> 5);
    const unsigned lane = threadIdx.x & 31;

    // Strided grid-stride over tiles: with grid sized for 2 tiles/warp this
    // executes exactly twice for (almost) every warp -> single balanced wave.
    for (int t = warpId; t < nwarpTiles; t += totalWarps)
        process_tile(A, B, O, t, lane);
}

// Scalar tail kernel (warp-per-row) for nrows % 32 != 0.
__global__ void spike_adder_tail(const float* __restrict__ A,
                                 const float* __restrict__ B,
                                 float* __restrict__ O,
                                 int rowStart, int nrows) {
    const int row = rowStart + blockIdx.x;
    const int lane = threadIdx.x & 31;
    if (row >= nrows) return;
    const size_t base = (size_t)row * 32 + lane;
    const unsigned ua = __ballot_sync(0xFFFFFFFFu, A[base] != 0.0f);
    const unsigned ub = __ballot_sync(0xFFFFFFFFu, B[base] != 0.0f);
    const unsigned res = spike_fp32_add(__brev(ua), __brev(ub));
    const unsigned f = ((unsigned)((int)(res << lane) >> 31)) & 0x3F800000u;
    O[base] = __uint_as_float(f);
}

extern "C" void kernel_launch(void* const* d_in, const int* in_sizes, int n_in,
                              void* d_out, int out_size) {
    const float* A = (const float*)d_in[0];
    const float* B = (const float*)d_in[1];
    float* O = (float*)d_out;

    const int nrows = in_sizes[0] / 32;
    const int nwarpTiles = nrows / 32;
    const int tailRows = nrows - nwarpTiles * 32;

    if (nwarpTiles > 0) {
        const int threads = 256;
        const int warpsPerBlock = threads / 32;         // 8
        const int tilesPerWarp = 2;
        int blocks = (nwarpTiles + warpsPerBlock * tilesPerWarp - 1) /
                     (warpsPerBlock * tilesPerWarp);    // 1024 for N=524288
        const int totalWarps = blocks * warpsPerBlock;
        spike_adder_kernel<<<blocks, threads>>>(
            (const unsigned*)A, (const unsigned*)B, O, nwarpTiles, totalWarps);
    }
    if (tailRows > 0) {
        spike_adder_tail<<<tailRows, 32>>>(A, B, O, nwarpTiles * 32, nrows);
    }
}